// round 11
// baseline (speedup 1.0000x reference)
#include <cuda_runtime.h>

// Problem constants
#define HW 4096            // 64*64
#define CIN 128
#define NOFF 18            // 2*K2
#define KD 1152            // CIN*9
#define NELEM (8 * 128 * HW)
#define PCH (8 * NOFF * HW)   // per-chunk partial stride = 589824

// Scratch (device globals; no allocation allowed)
__device__ float  g_h[NELEM];          // BN+ReLU output, 16 MB
__device__ float2 g_hp[NELEM];         // (h[x], h[x+1]) pairs, 32 MB
__device__ float  g_part[4 * PCH];     // conv18 partials (4 chunks)
__device__ float  g_part2[4 * PCH];    // dconv18 partials
__device__ unsigned g_wt2[KD * 128];   // dc_w tap-major tf32 [k2*128+c][oc]
__device__ float  g_wtA[KD * NOFF];    // off_w transposed [c*9+k2][18]
__device__ float  g_wtB[KD * NOFF];    // odc_w transposed

// ---------------------------------------------------------------------------
// K1: BN + ReLU; writes scalar g_h and pair g_hp.
// ---------------------------------------------------------------------------
__global__ void k_bnrelu(const float* __restrict__ x,
                         const float* __restrict__ gamma,
                         const float* __restrict__ beta,
                         const float* __restrict__ mean,
                         const float* __restrict__ var) {
    int i = blockIdx.x * blockDim.x + threadIdx.x;   // float4 index
    int c = (i >> 10) & 127;
    float s = rsqrtf(var[c] + 1e-5f) * gamma[c];
    float m = mean[c], bt = beta[c];
    float4 v = ((const float4*)x)[i];
    v.x = fmaxf((v.x - m) * s + bt, 0.f);
    v.y = fmaxf((v.y - m) * s + bt, 0.f);
    v.z = fmaxf((v.z - m) * s + bt, 0.f);
    v.w = fmaxf((v.w - m) * s + bt, 0.f);
    ((float4*)g_h)[i] = v;
    float nx = 0.f;
    int e = i * 4 + 4;
    if (e < NELEM) {
        int c2 = (e >> 12) & 127;
        float s2 = rsqrtf(var[c2] + 1e-5f) * gamma[c2];
        nx = fmaxf((x[e] - mean[c2]) * s2 + beta[c2], 0.f);
    }
    ((float4*)g_hp)[i * 2]     = make_float4(v.x, v.y, v.y, v.z);
    ((float4*)g_hp)[i * 2 + 1] = make_float4(v.z, v.w, v.w, nx);
}

// ---------------------------------------------------------------------------
// K0a: dc_w [oc][c*9+k2] -> g_wt2 tap-major tf32 [k2*128+c][oc].
// ---------------------------------------------------------------------------
__global__ void k_transpose_wt(const float* __restrict__ w) {
    int i = blockIdx.x * blockDim.x + threadIdx.x;   // 147456
    int oc = i & 127, jp = i >> 7;
    int k2 = jp >> 7, c = jp & 127;
    float v = w[oc * KD + c * 9 + k2];
    unsigned t;
    asm("cvt.rna.tf32.f32 %0, %1;" : "=r"(t) : "f"(v));
    g_wt2[i] = t;
}

// K0b: both 18-oc weights [18][KD] -> [KD][18] fp32.
__global__ void k_transpose_w18x2(const float* __restrict__ wA,
                                  const float* __restrict__ wB) {
    int i = blockIdx.x * blockDim.x + threadIdx.x;   // 2*KD*18 = 41472
    if (i >= 2 * KD * NOFF) return;
    int which = i >= KD * NOFF;
    int r = which ? i - KD * NOFF : i;
    int j = r / NOFF, oc = r - j * NOFF;
    const float* w = which ? wB : wA;
    float* dst = which ? g_wtB : g_wtA;
    dst[r] = w[oc * KD + j];
}

// ---------------------------------------------------------------------------
// Pair-gather bilinear decomposition (zero-OOB, torchvision semantics).
// ---------------------------------------------------------------------------
__device__ __forceinline__ void bilin_pair(
        float py, float px,
        float& e0, float& e1, float& wy0e, float& wy1e, int& o0, int& o1) {
    float fy0 = floorf(py), fx0 = floorf(px);
    float wy1 = py - fy0, wx1 = px - fx0;
    float wy0 = 1.f - wy1, wx0 = 1.f - wx1;
    int iy0 = (int)fy0, ix0 = (int)fx0;
    bool vy0 = ((unsigned)iy0 < 64u), vy1 = ((unsigned)(iy0 + 1) < 64u);
    bool vx0 = ((unsigned)ix0 < 64u), vx1 = ((unsigned)(ix0 + 1) < 64u);
    wy0e = vy0 ? wy0 : 0.f;
    wy1e = vy1 ? wy1 : 0.f;
    int xb;
    if (vx0)      { xb = ix0; e0 = wx0; e1 = vx1 ? wx1 : 0.f; }
    else if (vx1) { xb = 0;   e0 = wx1; e1 = 0.f; }
    else          { xb = 0;   e0 = 0.f; e1 = 0.f; }
    int y0c = min(max(iy0, 0), 63), y1c = min(max(iy0 + 1, 0), 63);
    o0 = y0c * 64 + xb;
    o1 = y1c * 64 + xb;
}

// ---------------------------------------------------------------------------
// K2/K3: 18-oc (deformable) conv, 4-way channel split (32 ch/chunk).
// Grid (256, 4), 128 thr = 2 rows. partIn==nullptr -> plain conv (g_h).
// Weight rows padded to 20 floats -> 4x LDS.128 + 1x LDS.64 per burst.
// ---------------------------------------------------------------------------
__global__ void __launch_bounds__(128) k_dc18v2(
        const float* __restrict__ partIn,   // offset partials or nullptr
        const float* __restrict__ obias,    // offset conv bias (deform only)
        const float* __restrict__ wtT,      // [KD][18] fp32
        float* __restrict__ partOut) {
    __shared__ float ws[32 * 9 * 20];       // 23040 B, rows padded to 20
    int tid = threadIdx.x;
    int row = blockIdx.x * 2 + (tid >> 6);
    int b = row >> 6, y = row & 63, x = tid & 63;
    int chunk = blockIdx.y;                 // 0..3
    int c0 = chunk * 32;

    const float* wsrc = wtT + c0 * 9 * NOFF;
    for (int i = tid; i < 32 * 9 * NOFF; i += 128) {
        int r = i / NOFF, cc = i - r * NOFF;
        ws[r * 20 + cc] = wsrc[i];
    }
    __syncthreads();

    float acc[NOFF];
#pragma unroll
    for (int o = 0; o < NOFF; o++) acc[o] = 0.f;

#define WFMA(S, WR)                                                      \
    {                                                                    \
        float4 w0 = *(const float4*)&(WR)[0];                            \
        float4 w1 = *(const float4*)&(WR)[4];                            \
        float4 w2 = *(const float4*)&(WR)[8];                            \
        float4 w3 = *(const float4*)&(WR)[12];                           \
        float2 w4 = *(const float2*)&(WR)[16];                           \
        acc[0]  = fmaf((S), w0.x, acc[0]);  acc[1]  = fmaf((S), w0.y, acc[1]);  \
        acc[2]  = fmaf((S), w0.z, acc[2]);  acc[3]  = fmaf((S), w0.w, acc[3]);  \
        acc[4]  = fmaf((S), w1.x, acc[4]);  acc[5]  = fmaf((S), w1.y, acc[5]);  \
        acc[6]  = fmaf((S), w1.z, acc[6]);  acc[7]  = fmaf((S), w1.w, acc[7]);  \
        acc[8]  = fmaf((S), w2.x, acc[8]);  acc[9]  = fmaf((S), w2.y, acc[9]);  \
        acc[10] = fmaf((S), w2.z, acc[10]); acc[11] = fmaf((S), w2.w, acc[11]); \
        acc[12] = fmaf((S), w3.x, acc[12]); acc[13] = fmaf((S), w3.y, acc[13]); \
        acc[14] = fmaf((S), w3.z, acc[14]); acc[15] = fmaf((S), w3.w, acc[15]); \
        acc[16] = fmaf((S), w4.x, acc[16]); acc[17] = fmaf((S), w4.y, acc[17]); \
    }

    if (partIn) {
        const float2* hb2 = (const float2*)g_hp + ((b << 7) + c0) * HW;
        int obase = b * NOFF * HW + y * 64 + x;
        for (int k2 = 0; k2 < 9; k2++) {
            float dy = obias[2 * k2], dx = obias[2 * k2 + 1];
            int oy = obase + (2 * k2) * HW, ox = oy + HW;
#pragma unroll
            for (int k = 0; k < 4; k++) {
                dy += partIn[k * PCH + oy];
                dx += partIn[k * PCH + ox];
            }
            float py = (float)(y - 1 + k2 / 3) + dy;
            float px = (float)(x - 1 + k2 % 3) + dx;
            float e0, e1, wy0, wy1; int o0, o1;
            bilin_pair(py, px, e0, e1, wy0, wy1, o0, o1);

            const float2* hp = hb2;
            for (int cl = 0; cl < 32; cl++, hp += HW) {
                float2 q0 = hp[o0], q1 = hp[o1];
                float s = e0 * (wy0 * q0.x + wy1 * q1.x)
                        + e1 * (wy0 * q0.y + wy1 * q1.y);
                const float* wr = ws + (cl * 9 + k2) * 20;
                WFMA(s, wr);
            }
        }
    } else {
        const float* hb = g_h + ((b << 7) + c0) * HW;
        for (int k2 = 0; k2 < 9; k2++) {
            int yy = y - 1 + k2 / 3, xx = x - 1 + k2 % 3;
            bool v = ((unsigned)yy < 64u) && ((unsigned)xx < 64u);
            int idx = v ? (yy * 64 + xx) : 0;
            const float* hp = hb;
            for (int cl = 0; cl < 32; cl++, hp += HW) {
                float s = v ? hp[idx] : 0.f;
                const float* wr = ws + (cl * 9 + k2) * 20;
                WFMA(s, wr);
            }
        }
    }
#undef WFMA

    float* dst = partOut + chunk * PCH + b * NOFF * HW + y * 64 + x;
#pragma unroll
    for (int o = 0; o < NOFF; o++) dst[o * HW] = acc[o];
}

// ---------------------------------------------------------------------------
// K4: 128-oc deformable conv — tf32 mma GEMM, 4-corner fp32 gathers (R6
// best-measured sampling), 256 thr, 3 blocks/SM. Offsets summed inline.
// ---------------------------------------------------------------------------
__device__ __forceinline__ void mma_tf32(float* d, const unsigned* a,
                                         unsigned b0, unsigned b1) {
    asm volatile(
        "mma.sync.aligned.m16n8k8.row.col.f32.tf32.tf32.f32 "
        "{%0,%1,%2,%3}, {%4,%5,%6,%7}, {%8,%9}, {%0,%1,%2,%3};"
        : "+f"(d[0]), "+f"(d[1]), "+f"(d[2]), "+f"(d[3])
        : "r"(a[0]), "r"(a[1]), "r"(a[2]), "r"(a[3]), "r"(b0), "r"(b1));
}

__global__ void __launch_bounds__(256, 3) k_dconv128_mma(
        const float* __restrict__ obias,    // odc_b
        const float* __restrict__ bias,     // dc_b
        float* __restrict__ out) {
    __shared__ float4   s_wq[576];      // 4 corner weights per (tap,px)
    __shared__ short4   s_iq[576];      // 4 corner indices
    __shared__ unsigned s_a[32][72];    // tf32 A tile, pad 72
    __shared__ unsigned s_b[32][136];   // tf32 B tile, pad 136

    int tid = threadIdx.x;
    int row = blockIdx.x;               // b*64 + y
    int b = row >> 6, y = row & 63;

    // Phase 0: offsets (4-partial sum + bias) -> 4-corner bilinear tables
    for (int t = tid; t < 576; t += 256) {
        int px = t & 63, k2 = t >> 6;
        int obase = b * NOFF * HW + y * 64 + px;
        float dy = obias[2 * k2], dx = obias[2 * k2 + 1];
        int oy = obase + (2 * k2) * HW, ox = oy + HW;
#pragma unroll
        for (int k = 0; k < 4; k++) {
            dy += g_part2[k * PCH + oy];
            dx += g_part2[k * PCH + ox];
        }
        float py  = (float)(y - 1 + k2 / 3) + dy;
        float pxf = (float)(px - 1 + k2 % 3) + dx;
        float fy0 = floorf(py), fx0 = floorf(pxf);
        float wy1 = py - fy0, wx1 = pxf - fx0;
        float wy0 = 1.f - wy1, wx0 = 1.f - wx1;
        int iy0 = (int)fy0, ix0 = (int)fx0;
        bool vy0 = ((unsigned)iy0 < 64u), vy1 = ((unsigned)(iy0 + 1) < 64u);
        bool vx0 = ((unsigned)ix0 < 64u), vx1 = ((unsigned)(ix0 + 1) < 64u);
        float4 w;
        w.x = (vy0 && vx0) ? wy0 * wx0 : 0.f;
        w.y = (vy0 && vx1) ? wy0 * wx1 : 0.f;
        w.z = (vy1 && vx0) ? wy1 * wx0 : 0.f;
        w.w = (vy1 && vx1) ? wy1 * wx1 : 0.f;
        int cy0 = min(max(iy0, 0), 63), cy1 = min(max(iy0 + 1, 0), 63);
        int cx0 = min(max(ix0, 0), 63), cx1 = min(max(ix0 + 1, 0), 63);
        s_wq[t] = w;
        s_iq[t] = make_short4((short)(cy0 * 64 + cx0), (short)(cy0 * 64 + cx1),
                              (short)(cy1 * 64 + cx0), (short)(cy1 * 64 + cx1));
    }
    __syncthreads();

    int lane = tid & 31, warp = tid >> 5;
    int pxw = (warp & 1) * 32;
    int ocw = (warp >> 1) * 32;
    int gid = lane >> 2, tig = lane & 3;

    float acc[2][4][4];
#pragma unroll
    for (int mt = 0; mt < 2; mt++)
#pragma unroll
        for (int nt = 0; nt < 4; nt++)
#pragma unroll
            for (int q = 0; q < 4; q++) acc[mt][nt][q] = 0.f;

    int px_s = tid & 63, cl0 = (tid >> 6) * 8;
    const float* hb = g_h + (b << 7) * HW;

    for (int kc = 0; kc < 36; kc++) {
        // Stage B tile
        {
            const uint4* src = (const uint4*)g_wt2 + kc * 1024;
            for (int i = tid; i < 1024; i += 256) {
                uint4 v = src[i];
                *(uint4*)&s_b[i >> 5][(i & 31) * 4] = v;
            }
        }
        // Sample A tile: 4-corner fp32 gathers
        {
            int k2 = kc >> 2, c0 = (kc & 3) * 32;
            float4 w = s_wq[k2 * 64 + px_s];
            short4 ixs = s_iq[k2 * 64 + px_s];
            int i0 = ixs.x, i1 = ixs.y, i2 = ixs.z, i3 = ixs.w;
            const float* hp = hb + (c0 + cl0) * HW;
#pragma unroll
            for (int i = 0; i < 8; i++, hp += HW) {
                float v = w.x * hp[i0] + w.y * hp[i1]
                        + w.z * hp[i2] + w.w * hp[i3];
                unsigned t32;
                asm("cvt.rna.tf32.f32 %0, %1;" : "=r"(t32) : "f"(v));
                s_a[cl0 + i][px_s] = t32;
            }
        }
        __syncthreads();

#pragma unroll
        for (int k0 = 0; k0 < 32; k0 += 8) {
            unsigned a[2][4];
#pragma unroll
            for (int mt = 0; mt < 2; mt++) {
                int pxb = pxw + mt * 16;
                a[mt][0] = s_a[k0 + tig][pxb + gid];
                a[mt][1] = s_a[k0 + tig][pxb + gid + 8];
                a[mt][2] = s_a[k0 + tig + 4][pxb + gid];
                a[mt][3] = s_a[k0 + tig + 4][pxb + gid + 8];
            }
#pragma unroll
            for (int nt = 0; nt < 4; nt++) {
                unsigned b0 = s_b[k0 + tig][ocw + nt * 8 + gid];
                unsigned b1 = s_b[k0 + tig + 4][ocw + nt * 8 + gid];
                mma_tf32(acc[0][nt], a[0], b0, b1);
                mma_tf32(acc[1][nt], a[1], b0, b1);
            }
        }
        __syncthreads();
    }

    int obase2 = (b << 7) * HW + y * 64;
#pragma unroll
    for (int nt = 0; nt < 4; nt++) {
        int oc0 = ocw + nt * 8 + 2 * tig;
        float bs0 = bias[oc0], bs1 = bias[oc0 + 1];
#pragma unroll
        for (int mt = 0; mt < 2; mt++) {
            int px0 = pxw + mt * 16 + gid;
            out[obase2 + oc0 * HW + px0]           = acc[mt][nt][0] + bs0;
            out[obase2 + (oc0 + 1) * HW + px0]     = acc[mt][nt][1] + bs1;
            out[obase2 + oc0 * HW + px0 + 8]       = acc[mt][nt][2] + bs0;
            out[obase2 + (oc0 + 1) * HW + px0 + 8] = acc[mt][nt][3] + bs1;
        }
    }
}

// ---------------------------------------------------------------------------
// Launch. Idx 3 (profiled) = deform k_dc18v2.
// Input order: x, bn_gamma, bn_beta, bn_mean, bn_var,
// off_w, off_b, odc_w, odc_b, dc_w, dc_b. Output: float32 [8,128,64,64].
// ---------------------------------------------------------------------------
extern "C" void kernel_launch(void* const* d_in, const int* in_sizes, int n_in,
                              void* d_out, int out_size) {
    const float* x     = (const float*)d_in[0];
    const float* gamma = (const float*)d_in[1];
    const float* beta  = (const float*)d_in[2];
    const float* mean  = (const float*)d_in[3];
    const float* var   = (const float*)d_in[4];
    const float* off_w = (const float*)d_in[5];
    const float* off_b = (const float*)d_in[6];
    const float* odc_w = (const float*)d_in[7];
    const float* odc_b = (const float*)d_in[8];
    const float* dc_w  = (const float*)d_in[9];
    const float* dc_b  = (const float*)d_in[10];
    float* out = (float*)d_out;

    float *wtA, *wtB, *part, *part2;
    cudaGetSymbolAddress((void**)&wtA,   g_wtA);
    cudaGetSymbolAddress((void**)&wtB,   g_wtB);
    cudaGetSymbolAddress((void**)&part,  g_part);
    cudaGetSymbolAddress((void**)&part2, g_part2);

    k_transpose_w18x2<<<162, 256>>>(off_w, odc_w);                     // 0
    k_bnrelu<<<4096, 256>>>(x, gamma, beta, mean, var);                // 1
    k_dc18v2<<<dim3(256, 4), 128>>>(nullptr, nullptr, wtA, part);      // 2
    k_dc18v2<<<dim3(256, 4), 128>>>(part, off_b, wtB, part2);          // 3 <- prof
    k_transpose_wt<<<576, 256>>>(dc_w);                                // 4
    k_dconv128_mma<<<512, 256>>>(odc_b, dc_b, out);                    // 5
}

// round 12
// speedup vs baseline: 1.1764x; 1.1764x over previous
#include <cuda_runtime.h>

// Problem constants
#define HW 4096            // 64*64
#define CIN 128
#define NOFF 18            // 2*K2
#define KD 1152            // CIN*9
#define NELEM (8 * 128 * HW)
#define PCH (8 * NOFF * HW)   // per-chunk partial stride = 589824

// Scratch (device globals; no allocation allowed)
__device__ float  g_h[NELEM];          // BN+ReLU output, 16 MB
__device__ float  g_part[4 * PCH];     // conv18 partials (4 chunks)
__device__ float  g_part2[4 * PCH];    // dconv18 partials
__device__ unsigned g_wt2[KD * 128];   // dc_w tap-major tf32 [k2*128+c][oc]
__device__ float  g_wtA[KD * NOFF];    // off_w transposed [c*9+k2][18]
__device__ float  g_wtB[KD * NOFF];    // odc_w transposed

// ---------------------------------------------------------------------------
// K_setup: fused BN+ReLU (blocks 0..4095), dc_w transpose->tf32 (4096..4671),
// both 18-oc weight transposes (4672..4833). One launch, 4834 blocks.
// ---------------------------------------------------------------------------
__global__ void k_setup(const float* __restrict__ x,
                        const float* __restrict__ gamma,
                        const float* __restrict__ beta,
                        const float* __restrict__ mean,
                        const float* __restrict__ var,
                        const float* __restrict__ dc_w,
                        const float* __restrict__ off_w,
                        const float* __restrict__ odc_w) {
    int bid = blockIdx.x, tid = threadIdx.x;
    if (bid < 4096) {
        // BN+ReLU, float4
        int i = bid * 256 + tid;
        int c = (i >> 10) & 127;
        float s = rsqrtf(var[c] + 1e-5f) * gamma[c];
        float m = mean[c], bt = beta[c];
        float4 v = ((const float4*)x)[i];
        v.x = fmaxf((v.x - m) * s + bt, 0.f);
        v.y = fmaxf((v.y - m) * s + bt, 0.f);
        v.z = fmaxf((v.z - m) * s + bt, 0.f);
        v.w = fmaxf((v.w - m) * s + bt, 0.f);
        ((float4*)g_h)[i] = v;
    } else if (bid < 4672) {
        // dc_w [oc][c*9+k2] -> g_wt2 tap-major tf32 [k2*128+c][oc]
        int i = (bid - 4096) * 256 + tid;        // 147456
        int oc = i & 127, jp = i >> 7;
        int k2 = jp >> 7, c = jp & 127;
        float v = dc_w[oc * KD + c * 9 + k2];
        unsigned t;
        asm("cvt.rna.tf32.f32 %0, %1;" : "=r"(t) : "f"(v));
        g_wt2[i] = t;
    } else {
        // both 18-oc weights [18][KD] -> [KD][18]
        int i = (bid - 4672) * 256 + tid;        // 2*KD*18 = 41472
        if (i < 2 * KD * NOFF) {
            int which = i >= KD * NOFF;
            int r = which ? i - KD * NOFF : i;
            int j = r / NOFF, oc = r - j * NOFF;
            const float* w = which ? odc_w : off_w;
            float* dst = which ? g_wtB : g_wtA;
            dst[r] = w[oc * KD + j];
        }
    }
}

// ---------------------------------------------------------------------------
// K2/K3: 18-oc (deformable) conv, 4-way channel split (32 ch/chunk).
// Grid (256, 4), 128 thr = 2 rows. R6-measured config: scalar 4-corner
// gathers from g_h, LDS.64 weight bursts, 18 register accumulators.
// partIn==nullptr -> plain conv. Deform: offsets = obias + sum of 4 partials.
// ---------------------------------------------------------------------------
__global__ void __launch_bounds__(128) k_dc18v2(
        const float* __restrict__ partIn,   // offset partials or nullptr
        const float* __restrict__ obias,    // offset conv bias (deform only)
        const float* __restrict__ wtT,      // [KD][18] fp32
        float* __restrict__ partOut) {
    __shared__ float ws[32 * 9 * NOFF];     // 20736 B
    int tid = threadIdx.x;
    int row = blockIdx.x * 2 + (tid >> 6);
    int b = row >> 6, y = row & 63, x = tid & 63;
    int chunk = blockIdx.y;                 // 0..3
    int c0 = chunk * 32;

    const float* wsrc = wtT + c0 * 9 * NOFF;
    for (int i = tid; i < 32 * 9 * NOFF; i += 128) ws[i] = wsrc[i];
    __syncthreads();

    float acc[NOFF];
#pragma unroll
    for (int o = 0; o < NOFF; o++) acc[o] = 0.f;

    const float* hb = g_h + ((b << 7) + c0) * HW;

    if (partIn) {
        int obase = b * NOFF * HW + y * 64 + x;
        for (int k2 = 0; k2 < 9; k2++) {
            float dy = obias[2 * k2], dx = obias[2 * k2 + 1];
            int oy = obase + (2 * k2) * HW, ox = oy + HW;
#pragma unroll
            for (int k = 0; k < 4; k++) {
                dy += partIn[k * PCH + oy];
                dx += partIn[k * PCH + ox];
            }
            float py = (float)(y - 1 + k2 / 3) + dy;
            float px = (float)(x - 1 + k2 % 3) + dx;
            float fy0 = floorf(py), fx0 = floorf(px);
            float wy1 = py - fy0, wx1 = px - fx0;
            float wy0 = 1.f - wy1, wx0 = 1.f - wx1;
            int iy0 = (int)fy0, ix0 = (int)fx0;
            int iy1 = iy0 + 1, ix1 = ix0 + 1;
            bool vy0 = ((unsigned)iy0 < 64u), vy1 = ((unsigned)iy1 < 64u);
            bool vx0 = ((unsigned)ix0 < 64u), vx1 = ((unsigned)ix1 < 64u);
            float w00 = (vy0 && vx0) ? wy0 * wx0 : 0.f;
            float w01 = (vy0 && vx1) ? wy0 * wx1 : 0.f;
            float w10 = (vy1 && vx0) ? wy1 * wx0 : 0.f;
            float w11 = (vy1 && vx1) ? wy1 * wx1 : 0.f;
            int cy0 = min(max(iy0, 0), 63), cy1 = min(max(iy1, 0), 63);
            int cx0 = min(max(ix0, 0), 63), cx1 = min(max(ix1, 0), 63);
            int i00 = cy0 * 64 + cx0, i01 = cy0 * 64 + cx1;
            int i10 = cy1 * 64 + cx0, i11 = cy1 * 64 + cx1;

            const float* hp = hb;
            for (int cl = 0; cl < 32; cl++, hp += HW) {
                float s = w00 * hp[i00] + w01 * hp[i01]
                        + w10 * hp[i10] + w11 * hp[i11];
                const float* wr = ws + (cl * 9 + k2) * NOFF;
#pragma unroll
                for (int op = 0; op < 9; op++) {
                    float2 w = *(const float2*)&wr[2 * op];
                    acc[2 * op]     = fmaf(s, w.x, acc[2 * op]);
                    acc[2 * op + 1] = fmaf(s, w.y, acc[2 * op + 1]);
                }
            }
        }
    } else {
        for (int k2 = 0; k2 < 9; k2++) {
            int yy = y - 1 + k2 / 3, xx = x - 1 + k2 % 3;
            bool v = ((unsigned)yy < 64u) && ((unsigned)xx < 64u);
            int idx = v ? (yy * 64 + xx) : 0;
            const float* hp = hb;
            for (int cl = 0; cl < 32; cl++, hp += HW) {
                float s = v ? hp[idx] : 0.f;
                const float* wr = ws + (cl * 9 + k2) * NOFF;
#pragma unroll
                for (int op = 0; op < 9; op++) {
                    float2 w = *(const float2*)&wr[2 * op];
                    acc[2 * op]     = fmaf(s, w.x, acc[2 * op]);
                    acc[2 * op + 1] = fmaf(s, w.y, acc[2 * op + 1]);
                }
            }
        }
    }

    float* dst = partOut + chunk * PCH + b * NOFF * HW + y * 64 + x;
#pragma unroll
    for (int o = 0; o < NOFF; o++) dst[o * HW] = acc[o];
}

// ---------------------------------------------------------------------------
// K4: 128-oc deformable conv — tf32 mma GEMM. Exact R6-measured config:
// 512 blocks x 256 thr, (256,2), static smem, single buffer, 4-corner
// gathers. Only change: offsets = odc_b + sum of 4 partials inline.
// ---------------------------------------------------------------------------
__device__ __forceinline__ void mma_tf32(float* d, const unsigned* a,
                                         unsigned b0, unsigned b1) {
    asm volatile(
        "mma.sync.aligned.m16n8k8.row.col.f32.tf32.tf32.f32 "
        "{%0,%1,%2,%3}, {%4,%5,%6,%7}, {%8,%9}, {%0,%1,%2,%3};"
        : "+f"(d[0]), "+f"(d[1]), "+f"(d[2]), "+f"(d[3])
        : "r"(a[0]), "r"(a[1]), "r"(a[2]), "r"(a[3]), "r"(b0), "r"(b1));
}

__global__ void __launch_bounds__(256, 2) k_dconv128_mma(
        const float* __restrict__ obias,    // odc_b
        const float* __restrict__ bias,     // dc_b
        float* __restrict__ out) {
    __shared__ float4   s_wq[576];      // bilinear weights [k2*64+px]
    __shared__ int4     s_iq[576];      // corner indices
    __shared__ unsigned s_a[32][72];    // tf32 A tile, pad 72
    __shared__ unsigned s_b[32][136];   // tf32 B tile, pad 136

    int tid = threadIdx.x;
    int row = blockIdx.x;               // b*64 + y
    int b = row >> 6, y = row & 63;

    // Phase 0: offsets (4-partial sum + bias) -> bilinear tables
    for (int t = tid; t < 576; t += 256) {
        int px = t & 63, k2 = t >> 6;
        int obase = b * NOFF * HW + y * 64 + px;
        float dy = obias[2 * k2], dx = obias[2 * k2 + 1];
        int oy = obase + (2 * k2) * HW, ox = oy + HW;
#pragma unroll
        for (int k = 0; k < 4; k++) {
            dy += g_part2[k * PCH + oy];
            dx += g_part2[k * PCH + ox];
        }
        float py  = (float)(y - 1 + k2 / 3) + dy;
        float pxf = (float)(px - 1 + k2 % 3) + dx;
        float fy0 = floorf(py), fx0 = floorf(pxf);
        float wy1 = py - fy0, wx1 = pxf - fx0;
        float wy0 = 1.f - wy1, wx0 = 1.f - wx1;
        int iy0 = (int)fy0, ix0 = (int)fx0;
        int iy1 = iy0 + 1, ix1 = ix0 + 1;
        bool vy0 = ((unsigned)iy0 < 64u), vy1 = ((unsigned)iy1 < 64u);
        bool vx0 = ((unsigned)ix0 < 64u), vx1 = ((unsigned)ix1 < 64u);
        float4 w;
        w.x = (vy0 && vx0) ? wy0 * wx0 : 0.f;
        w.y = (vy0 && vx1) ? wy0 * wx1 : 0.f;
        w.z = (vy1 && vx0) ? wy1 * wx0 : 0.f;
        w.w = (vy1 && vx1) ? wy1 * wx1 : 0.f;
        int cy0 = min(max(iy0, 0), 63), cy1 = min(max(iy1, 0), 63);
        int cx0 = min(max(ix0, 0), 63), cx1 = min(max(ix1, 0), 63);
        s_wq[t] = w;
        s_iq[t] = make_int4(cy0 * 64 + cx0, cy0 * 64 + cx1,
                            cy1 * 64 + cx0, cy1 * 64 + cx1);
    }
    __syncthreads();

    int lane = tid & 31, warp = tid >> 5;
    int pxw = (warp & 1) * 32;          // warp px base
    int ocw = (warp >> 1) * 32;         // warp oc base
    int gid = lane >> 2, tig = lane & 3;

    float acc[2][4][4];
#pragma unroll
    for (int mt = 0; mt < 2; mt++)
#pragma unroll
        for (int nt = 0; nt < 4; nt++)
#pragma unroll
            for (int q = 0; q < 4; q++) acc[mt][nt][q] = 0.f;

    int px_s = tid & 63, cl0 = (tid >> 6) * 8;   // 8 samples/thread
    const float* hb = g_h + (b << 7) * HW;

    for (int kc = 0; kc < 36; kc++) {
        int k2 = kc >> 2, c0 = (kc & 3) * 32;

        // Stage B tile (32 x 128 tf32)
        {
            const uint4* src = (const uint4*)g_wt2 + kc * 1024;
            for (int i = tid; i < 1024; i += 256) {
                uint4 v = src[i];
                *(uint4*)&s_b[i >> 5][(i & 31) * 4] = v;
            }
        }
        // Sample A tile: 4-corner gathers, weights/indices in regs
        {
            float4 w = s_wq[k2 * 64 + px_s];
            int4  ix = s_iq[k2 * 64 + px_s];
            const float* hp = hb + (c0 + cl0) * HW;
#pragma unroll
            for (int i = 0; i < 8; i++, hp += HW) {
                float v = w.x * hp[ix.x] + w.y * hp[ix.y]
                        + w.z * hp[ix.z] + w.w * hp[ix.w];
                unsigned t32;
                asm("cvt.rna.tf32.f32 %0, %1;" : "=r"(t32) : "f"(v));
                s_a[cl0 + i][px_s] = t32;
            }
        }
        __syncthreads();

        // MMA phase: 4 k8-steps x (2 m-tiles x 4 n-tiles)
#pragma unroll
        for (int k0 = 0; k0 < 32; k0 += 8) {
            unsigned a[2][4];
#pragma unroll
            for (int mt = 0; mt < 2; mt++) {
                int pxb = pxw + mt * 16;
                a[mt][0] = s_a[k0 + tig][pxb + gid];
                a[mt][1] = s_a[k0 + tig][pxb + gid + 8];
                a[mt][2] = s_a[k0 + tig + 4][pxb + gid];
                a[mt][3] = s_a[k0 + tig + 4][pxb + gid + 8];
            }
#pragma unroll
            for (int nt = 0; nt < 4; nt++) {
                unsigned b0 = s_b[k0 + tig][ocw + nt * 8 + gid];
                unsigned b1 = s_b[k0 + tig + 4][ocw + nt * 8 + gid];
                mma_tf32(acc[0][nt], a[0], b0, b1);
                mma_tf32(acc[1][nt], a[1], b0, b1);
            }
        }
        __syncthreads();
    }

    // Epilogue: bias + stores
    int obase2 = (b << 7) * HW + y * 64;
#pragma unroll
    for (int nt = 0; nt < 4; nt++) {
        int oc0 = ocw + nt * 8 + 2 * tig;
        float bs0 = bias[oc0], bs1 = bias[oc0 + 1];
#pragma unroll
        for (int mt = 0; mt < 2; mt++) {
            int px0 = pxw + mt * 16 + gid;
            out[obase2 + oc0 * HW + px0]           = acc[mt][nt][0] + bs0;
            out[obase2 + (oc0 + 1) * HW + px0]     = acc[mt][nt][1] + bs1;
            out[obase2 + oc0 * HW + px0 + 8]       = acc[mt][nt][2] + bs0;
            out[obase2 + (oc0 + 1) * HW + px0 + 8] = acc[mt][nt][3] + bs1;
        }
    }
}

// ---------------------------------------------------------------------------
// Launch: exactly 4 launches; index 3 (= ncu's profiled slot) is mma128.
// Input order: x, bn_gamma, bn_beta, bn_mean, bn_var,
// off_w, off_b, odc_w, odc_b, dc_w, dc_b. Output: float32 [8,128,64,64].
// ---------------------------------------------------------------------------
extern "C" void kernel_launch(void* const* d_in, const int* in_sizes, int n_in,
                              void* d_out, int out_size) {
    const float* x     = (const float*)d_in[0];
    const float* gamma = (const float*)d_in[1];
    const float* beta  = (const float*)d_in[2];
    const float* mean  = (const float*)d_in[3];
    const float* var   = (const float*)d_in[4];
    const float* off_w = (const float*)d_in[5];
    const float* off_b = (const float*)d_in[6];
    const float* odc_w = (const float*)d_in[7];
    const float* odc_b = (const float*)d_in[8];
    const float* dc_w  = (const float*)d_in[9];
    const float* dc_b  = (const float*)d_in[10];
    float* out = (float*)d_out;

    float *wtA, *wtB, *part, *part2;
    cudaGetSymbolAddress((void**)&wtA,   g_wtA);
    cudaGetSymbolAddress((void**)&wtB,   g_wtB);
    cudaGetSymbolAddress((void**)&part,  g_part);
    cudaGetSymbolAddress((void**)&part2, g_part2);

    k_setup<<<4834, 256>>>(x, gamma, beta, mean, var, dc_w, off_w, odc_w); // 0
    k_dc18v2<<<dim3(256, 4), 128>>>(nullptr, nullptr, wtA, part);          // 1
    k_dc18v2<<<dim3(256, 4), 128>>>(part, off_b, wtB, part2);              // 2
    k_dconv128_mma<<<512, 256>>>(odc_b, dc_b, out);                        // 3 <- prof
}

// round 13
// speedup vs baseline: 1.1961x; 1.0167x over previous
#include <cuda_runtime.h>

// Problem constants
#define HW 4096            // 64*64
#define CIN 128
#define NOFF 18            // 2*K2
#define KD 1152            // CIN*9
#define NELEM (8 * 128 * HW)
#define PCH (8 * NOFF * HW)   // per-chunk partial stride = 589824

// Scratch (device globals; no allocation allowed)
__device__ float  g_h[NELEM];          // BN+ReLU output, 16 MB
__device__ float  g_part[4 * PCH];     // conv18 partials (4 chunks)
__device__ float  g_part2[4 * PCH];    // dconv18 partials
__device__ unsigned g_wt2[KD * 128];   // dc_w tap-major tf32 [k2*128+c][oc]
__device__ float  g_wtA[KD * NOFF];    // off_w transposed [c*9+k2][18]
__device__ float  g_wtB[KD * NOFF];    // odc_w transposed

// ---------------------------------------------------------------------------
// K_setup: fused BN+ReLU (blocks 0..4095), dc_w transpose->tf32 (4096..4671),
// both 18-oc weight transposes (4672..4833). One launch, 4834 blocks.
// ---------------------------------------------------------------------------
__global__ void k_setup(const float* __restrict__ x,
                        const float* __restrict__ gamma,
                        const float* __restrict__ beta,
                        const float* __restrict__ mean,
                        const float* __restrict__ var,
                        const float* __restrict__ dc_w,
                        const float* __restrict__ off_w,
                        const float* __restrict__ odc_w) {
    int bid = blockIdx.x, tid = threadIdx.x;
    if (bid < 4096) {
        int i = bid * 256 + tid;
        int c = (i >> 10) & 127;
        float s = rsqrtf(var[c] + 1e-5f) * gamma[c];
        float m = mean[c], bt = beta[c];
        float4 v = ((const float4*)x)[i];
        v.x = fmaxf((v.x - m) * s + bt, 0.f);
        v.y = fmaxf((v.y - m) * s + bt, 0.f);
        v.z = fmaxf((v.z - m) * s + bt, 0.f);
        v.w = fmaxf((v.w - m) * s + bt, 0.f);
        ((float4*)g_h)[i] = v;
    } else if (bid < 4672) {
        int i = (bid - 4096) * 256 + tid;        // 147456
        int oc = i & 127, jp = i >> 7;
        int k2 = jp >> 7, c = jp & 127;
        float v = dc_w[oc * KD + c * 9 + k2];
        unsigned t;
        asm("cvt.rna.tf32.f32 %0, %1;" : "=r"(t) : "f"(v));
        g_wt2[i] = t;
    } else {
        int i = (bid - 4672) * 256 + tid;        // 2*KD*18 = 41472
        if (i < 2 * KD * NOFF) {
            int which = i >= KD * NOFF;
            int r = which ? i - KD * NOFF : i;
            int j = r / NOFF, oc = r - j * NOFF;
            const float* w = which ? odc_w : off_w;
            float* dst = which ? g_wtB : g_wtA;
            dst[r] = w[oc * KD + j];
        }
    }
}

// ---------------------------------------------------------------------------
// K2/K3: 18-oc (deformable) conv, 4-way channel split (unchanged from R12).
// ---------------------------------------------------------------------------
__global__ void __launch_bounds__(128) k_dc18v2(
        const float* __restrict__ partIn,   // offset partials or nullptr
        const float* __restrict__ obias,    // offset conv bias (deform only)
        const float* __restrict__ wtT,      // [KD][18] fp32
        float* __restrict__ partOut) {
    __shared__ float ws[32 * 9 * NOFF];     // 20736 B
    int tid = threadIdx.x;
    int row = blockIdx.x * 2 + (tid >> 6);
    int b = row >> 6, y = row & 63, x = tid & 63;
    int chunk = blockIdx.y;                 // 0..3
    int c0 = chunk * 32;

    const float* wsrc = wtT + c0 * 9 * NOFF;
    for (int i = tid; i < 32 * 9 * NOFF; i += 128) ws[i] = wsrc[i];
    __syncthreads();

    float acc[NOFF];
#pragma unroll
    for (int o = 0; o < NOFF; o++) acc[o] = 0.f;

    const float* hb = g_h + ((b << 7) + c0) * HW;

    if (partIn) {
        int obase = b * NOFF * HW + y * 64 + x;
        for (int k2 = 0; k2 < 9; k2++) {
            float dy = obias[2 * k2], dx = obias[2 * k2 + 1];
            int oy = obase + (2 * k2) * HW, ox = oy + HW;
#pragma unroll
            for (int k = 0; k < 4; k++) {
                dy += partIn[k * PCH + oy];
                dx += partIn[k * PCH + ox];
            }
            float py = (float)(y - 1 + k2 / 3) + dy;
            float px = (float)(x - 1 + k2 % 3) + dx;
            float fy0 = floorf(py), fx0 = floorf(px);
            float wy1 = py - fy0, wx1 = px - fx0;
            float wy0 = 1.f - wy1, wx0 = 1.f - wx1;
            int iy0 = (int)fy0, ix0 = (int)fx0;
            int iy1 = iy0 + 1, ix1 = ix0 + 1;
            bool vy0 = ((unsigned)iy0 < 64u), vy1 = ((unsigned)iy1 < 64u);
            bool vx0 = ((unsigned)ix0 < 64u), vx1 = ((unsigned)ix1 < 64u);
            float w00 = (vy0 && vx0) ? wy0 * wx0 : 0.f;
            float w01 = (vy0 && vx1) ? wy0 * wx1 : 0.f;
            float w10 = (vy1 && vx0) ? wy1 * wx0 : 0.f;
            float w11 = (vy1 && vx1) ? wy1 * wx1 : 0.f;
            int cy0 = min(max(iy0, 0), 63), cy1 = min(max(iy1, 0), 63);
            int cx0 = min(max(ix0, 0), 63), cx1 = min(max(ix1, 0), 63);
            int i00 = cy0 * 64 + cx0, i01 = cy0 * 64 + cx1;
            int i10 = cy1 * 64 + cx0, i11 = cy1 * 64 + cx1;

            const float* hp = hb;
            for (int cl = 0; cl < 32; cl++, hp += HW) {
                float s = w00 * hp[i00] + w01 * hp[i01]
                        + w10 * hp[i10] + w11 * hp[i11];
                const float* wr = ws + (cl * 9 + k2) * NOFF;
#pragma unroll
                for (int op = 0; op < 9; op++) {
                    float2 w = *(const float2*)&wr[2 * op];
                    acc[2 * op]     = fmaf(s, w.x, acc[2 * op]);
                    acc[2 * op + 1] = fmaf(s, w.y, acc[2 * op + 1]);
                }
            }
        }
    } else {
        for (int k2 = 0; k2 < 9; k2++) {
            int yy = y - 1 + k2 / 3, xx = x - 1 + k2 % 3;
            bool v = ((unsigned)yy < 64u) && ((unsigned)xx < 64u);
            int idx = v ? (yy * 64 + xx) : 0;
            const float* hp = hb;
            for (int cl = 0; cl < 32; cl++, hp += HW) {
                float s = v ? hp[idx] : 0.f;
                const float* wr = ws + (cl * 9 + k2) * NOFF;
#pragma unroll
                for (int op = 0; op < 9; op++) {
                    float2 w = *(const float2*)&wr[2 * op];
                    acc[2 * op]     = fmaf(s, w.x, acc[2 * op]);
                    acc[2 * op + 1] = fmaf(s, w.y, acc[2 * op + 1]);
                }
            }
        }
    }

    float* dst = partOut + chunk * PCH + b * NOFF * HW + y * 64 + x;
#pragma unroll
    for (int o = 0; o < NOFF; o++) dst[o * HW] = acc[o];
}

// ---------------------------------------------------------------------------
// K4: 128-oc deformable conv — tf32 mma GEMM v3.
// Tile 32px x 128oc, 128 threads (4 warps; each 32px x 32oc), grid 1024.
// ~31 KB smem, ~94 regs -> 5 blocks/SM (20 warps, 5 sync domains).
// B tile staged via cp.async (overlaps the gather fill).
// ---------------------------------------------------------------------------
__device__ __forceinline__ void mma_tf32(float* d, const unsigned* a,
                                         unsigned b0, unsigned b1) {
    asm volatile(
        "mma.sync.aligned.m16n8k8.row.col.f32.tf32.tf32.f32 "
        "{%0,%1,%2,%3}, {%4,%5,%6,%7}, {%8,%9}, {%0,%1,%2,%3};"
        : "+f"(d[0]), "+f"(d[1]), "+f"(d[2]), "+f"(d[3])
        : "r"(a[0]), "r"(a[1]), "r"(a[2]), "r"(a[3]), "r"(b0), "r"(b1));
}

__global__ void __launch_bounds__(128) k_dconv128_mma(
        const float* __restrict__ obias,    // odc_b
        const float* __restrict__ bias,     // dc_b
        float* __restrict__ out) {
    __shared__ float4   s_wq[288];      // bilinear weights [k2*32+px]
    __shared__ int4     s_iq[288];      // corner indices
    __shared__ unsigned s_a[32][40];    // tf32 A tile [k][px], pad 40
    __shared__ unsigned s_b[32][136];   // tf32 B tile [k][oc], pad 136

    int tid = threadIdx.x;
    int blk = blockIdx.x;               // 1024 blocks
    int row = blk >> 1;
    int b = row >> 6, y = row & 63, x0 = (blk & 1) * 32;

    // Phase 0: offsets (4-partial sum + bias) -> bilinear tables, 32px x 9 taps
    for (int t = tid; t < 288; t += 128) {
        int px = t & 31, k2 = t >> 5;
        int x = x0 + px;
        int obase = b * NOFF * HW + y * 64 + x;
        float dy = obias[2 * k2], dx = obias[2 * k2 + 1];
        int oy = obase + (2 * k2) * HW, ox = oy + HW;
#pragma unroll
        for (int k = 0; k < 4; k++) {
            dy += g_part2[k * PCH + oy];
            dx += g_part2[k * PCH + ox];
        }
        float py  = (float)(y - 1 + k2 / 3) + dy;
        float pxf = (float)(x - 1 + k2 % 3) + dx;
        float fy0 = floorf(py), fx0 = floorf(pxf);
        float wy1 = py - fy0, wx1 = pxf - fx0;
        float wy0 = 1.f - wy1, wx0 = 1.f - wx1;
        int iy0 = (int)fy0, ix0 = (int)fx0;
        int iy1 = iy0 + 1, ix1 = ix0 + 1;
        bool vy0 = ((unsigned)iy0 < 64u), vy1 = ((unsigned)iy1 < 64u);
        bool vx0 = ((unsigned)ix0 < 64u), vx1 = ((unsigned)ix1 < 64u);
        float4 w;
        w.x = (vy0 && vx0) ? wy0 * wx0 : 0.f;
        w.y = (vy0 && vx1) ? wy0 * wx1 : 0.f;
        w.z = (vy1 && vx0) ? wy1 * wx0 : 0.f;
        w.w = (vy1 && vx1) ? wy1 * wx1 : 0.f;
        int cy0 = min(max(iy0, 0), 63), cy1 = min(max(iy1, 0), 63);
        int cx0 = min(max(ix0, 0), 63), cx1 = min(max(ix1, 0), 63);
        s_wq[t] = w;
        s_iq[t] = make_int4(cy0 * 64 + cx0, cy0 * 64 + cx1,
                            cy1 * 64 + cx0, cy1 * 64 + cx1);
    }
    __syncthreads();

    int lane = tid & 31, warp = tid >> 5;
    int ocw = warp * 32;                // warp oc base (all warps share 32 px)
    int gid = lane >> 2, tig = lane & 3;

    float acc[2][4][4];
#pragma unroll
    for (int mt = 0; mt < 2; mt++)
#pragma unroll
        for (int nt = 0; nt < 4; nt++)
#pragma unroll
            for (int q = 0; q < 4; q++) acc[mt][nt][q] = 0.f;

    int px_s = tid & 31, cl0 = (tid >> 5) * 8;   // 8 samples/thread
    const float* hb = g_h + (b << 7) * HW;

    for (int kc = 0; kc < 36; kc++) {
        int k2 = kc >> 2, c0 = (kc & 3) * 32;

        // Stage B tile via cp.async: 1024 uint4 / 128 thr = 8 each
        {
            const uint4* src = (const uint4*)g_wt2 + kc * 1024;
#pragma unroll
            for (int j = 0; j < 8; j++) {
                int i = tid + j * 128;
                unsigned dst = (unsigned)__cvta_generic_to_shared(
                    &s_b[i >> 5][(i & 31) * 4]);
                asm volatile("cp.async.cg.shared.global [%0], [%1], 16;"
                             :: "r"(dst), "l"(src + i));
            }
            asm volatile("cp.async.commit_group;");
        }
        // Sample A tile: 32px x 32ch, 4-corner gathers (overlaps cp.async)
        {
            float4 w = s_wq[k2 * 32 + px_s];
            int4  ix = s_iq[k2 * 32 + px_s];
            const float* hp = hb + (c0 + cl0) * HW;
#pragma unroll
            for (int i = 0; i < 8; i++, hp += HW) {
                float v = w.x * hp[ix.x] + w.y * hp[ix.y]
                        + w.z * hp[ix.z] + w.w * hp[ix.w];
                unsigned t32;
                asm("cvt.rna.tf32.f32 %0, %1;" : "=r"(t32) : "f"(v));
                s_a[cl0 + i][px_s] = t32;
            }
        }
        asm volatile("cp.async.wait_group 0;");
        __syncthreads();

        // MMA phase: 4 k8-steps x (2 m-tiles x 4 n-tiles)
#pragma unroll
        for (int k0 = 0; k0 < 32; k0 += 8) {
            unsigned a[2][4];
#pragma unroll
            for (int mt = 0; mt < 2; mt++) {
                int pxb = mt * 16;
                a[mt][0] = s_a[k0 + tig][pxb + gid];
                a[mt][1] = s_a[k0 + tig][pxb + gid + 8];
                a[mt][2] = s_a[k0 + tig + 4][pxb + gid];
                a[mt][3] = s_a[k0 + tig + 4][pxb + gid + 8];
            }
#pragma unroll
            for (int nt = 0; nt < 4; nt++) {
                unsigned b0 = s_b[k0 + tig][ocw + nt * 8 + gid];
                unsigned b1 = s_b[k0 + tig + 4][ocw + nt * 8 + gid];
                mma_tf32(acc[0][nt], a[0], b0, b1);
                mma_tf32(acc[1][nt], a[1], b0, b1);
            }
        }
        __syncthreads();
    }

    // Epilogue: bias + stores
    int obase2 = (b << 7) * HW + y * 64 + x0;
#pragma unroll
    for (int nt = 0; nt < 4; nt++) {
        int oc0 = ocw + nt * 8 + 2 * tig;
        float bs0 = bias[oc0], bs1 = bias[oc0 + 1];
#pragma unroll
        for (int mt = 0; mt < 2; mt++) {
            int px0 = mt * 16 + gid;
            out[obase2 + oc0 * HW + px0]           = acc[mt][nt][0] + bs0;
            out[obase2 + (oc0 + 1) * HW + px0]     = acc[mt][nt][1] + bs1;
            out[obase2 + oc0 * HW + px0 + 8]       = acc[mt][nt][2] + bs0;
            out[obase2 + (oc0 + 1) * HW + px0 + 8] = acc[mt][nt][3] + bs1;
        }
    }
}

// ---------------------------------------------------------------------------
// Launch: 4 launches; index 3 (ncu's profiled slot) = mma128.
// Input order: x, bn_gamma, bn_beta, bn_mean, bn_var,
// off_w, off_b, odc_w, odc_b, dc_w, dc_b. Output: float32 [8,128,64,64].
// ---------------------------------------------------------------------------
extern "C" void kernel_launch(void* const* d_in, const int* in_sizes, int n_in,
                              void* d_out, int out_size) {
    const float* x     = (const float*)d_in[0];
    const float* gamma = (const float*)d_in[1];
    const float* beta  = (const float*)d_in[2];
    const float* mean  = (const float*)d_in[3];
    const float* var   = (const float*)d_in[4];
    const float* off_w = (const float*)d_in[5];
    const float* off_b = (const float*)d_in[6];
    const float* odc_w = (const float*)d_in[7];
    const float* odc_b = (const float*)d_in[8];
    const float* dc_w  = (const float*)d_in[9];
    const float* dc_b  = (const float*)d_in[10];
    float* out = (float*)d_out;

    float *wtA, *wtB, *part, *part2;
    cudaGetSymbolAddress((void**)&wtA,   g_wtA);
    cudaGetSymbolAddress((void**)&wtB,   g_wtB);
    cudaGetSymbolAddress((void**)&part,  g_part);
    cudaGetSymbolAddress((void**)&part2, g_part2);

    k_setup<<<4834, 256>>>(x, gamma, beta, mean, var, dc_w, off_w, odc_w); // 0
    k_dc18v2<<<dim3(256, 4), 128>>>(nullptr, nullptr, wtA, part);          // 1
    k_dc18v2<<<dim3(256, 4), 128>>>(part, off_b, wtB, part2);              // 2
    k_dconv128_mma<<<1024, 128>>>(odc_b, dc_b, out);                       // 3 <- prof
}

// round 15
// speedup vs baseline: 1.3115x; 1.0965x over previous
#include <cuda_runtime.h>

// Problem constants
#define HW 4096            // 64*64
#define CIN 128
#define NOFF 18            // 2*K2
#define KD 1152            // CIN*9
#define NELEM (8 * 128 * HW)
#define PCH (8 * NOFF * HW)   // per-chunk partial stride = 589824

// Scratch (device globals; no allocation allowed)
__device__ float  g_h[NELEM];          // BN+ReLU output, 16 MB
__device__ float  g_part[4 * PCH];     // conv18 partials (4 chunks)
__device__ float  g_part2[4 * PCH];    // dconv18 partials
__device__ unsigned g_wt2[KD * 128];   // dc_w tap-major tf32 [k2*128+c][oc]
__device__ float  g_wtA[KD * NOFF];    // off_w transposed [c*9+k2][18]
__device__ float  g_wtB[KD * NOFF];    // odc_w transposed

// ---------------------------------------------------------------------------
// K_setup: fused BN+ReLU (blocks 0..4095), dc_w transpose->tf32 (4096..4671),
// both 18-oc weight transposes (4672..4833). One launch, 4834 blocks.
// ---------------------------------------------------------------------------
__global__ void k_setup(const float* __restrict__ x,
                        const float* __restrict__ gamma,
                        const float* __restrict__ beta,
                        const float* __restrict__ mean,
                        const float* __restrict__ var,
                        const float* __restrict__ dc_w,
                        const float* __restrict__ off_w,
                        const float* __restrict__ odc_w) {
    int bid = blockIdx.x, tid = threadIdx.x;
    if (bid < 4096) {
        int i = bid * 256 + tid;
        int c = (i >> 10) & 127;
        float s = rsqrtf(var[c] + 1e-5f) * gamma[c];
        float m = mean[c], bt = beta[c];
        float4 v = ((const float4*)x)[i];
        v.x = fmaxf((v.x - m) * s + bt, 0.f);
        v.y = fmaxf((v.y - m) * s + bt, 0.f);
        v.z = fmaxf((v.z - m) * s + bt, 0.f);
        v.w = fmaxf((v.w - m) * s + bt, 0.f);
        ((float4*)g_h)[i] = v;
    } else if (bid < 4672) {
        int i = (bid - 4096) * 256 + tid;        // 147456
        int oc = i & 127, jp = i >> 7;
        int k2 = jp >> 7, c = jp & 127;
        float v = dc_w[oc * KD + c * 9 + k2];
        unsigned t;
        asm("cvt.rna.tf32.f32 %0, %1;" : "=r"(t) : "f"(v));
        g_wt2[i] = t;
    } else {
        int i = (bid - 4672) * 256 + tid;        // 2*KD*18 = 41472
        if (i < 2 * KD * NOFF) {
            int which = i >= KD * NOFF;
            int r = which ? i - KD * NOFF : i;
            int j = r / NOFF, oc = r - j * NOFF;
            const float* w = which ? odc_w : off_w;
            float* dst = which ? g_wtB : g_wtA;
            dst[r] = w[oc * KD + j];
        }
    }
}

// ---------------------------------------------------------------------------
// K2/K3: 18-oc (deformable) conv, 4-way channel split (frozen from R12).
// ---------------------------------------------------------------------------
__global__ void __launch_bounds__(128) k_dc18v2(
        const float* __restrict__ partIn,   // offset partials or nullptr
        const float* __restrict__ obias,    // offset conv bias (deform only)
        const float* __restrict__ wtT,      // [KD][18] fp32
        float* __restrict__ partOut) {
    __shared__ float ws[32 * 9 * NOFF];     // 20736 B
    int tid = threadIdx.x;
    int row = blockIdx.x * 2 + (tid >> 6);
    int b = row >> 6, y = row & 63, x = tid & 63;
    int chunk = blockIdx.y;                 // 0..3
    int c0 = chunk * 32;

    const float* wsrc = wtT + c0 * 9 * NOFF;
    for (int i = tid; i < 32 * 9 * NOFF; i += 128) ws[i] = wsrc[i];
    __syncthreads();

    float acc[NOFF];
#pragma unroll
    for (int o = 0; o < NOFF; o++) acc[o] = 0.f;

    const float* hb = g_h + ((b << 7) + c0) * HW;

    if (partIn) {
        int obase = b * NOFF * HW + y * 64 + x;
        for (int k2 = 0; k2 < 9; k2++) {
            float dy = obias[2 * k2], dx = obias[2 * k2 + 1];
            int oy = obase + (2 * k2) * HW, ox = oy + HW;
#pragma unroll
            for (int k = 0; k < 4; k++) {
                dy += partIn[k * PCH + oy];
                dx += partIn[k * PCH + ox];
            }
            float py = (float)(y - 1 + k2 / 3) + dy;
            float px = (float)(x - 1 + k2 % 3) + dx;
            float fy0 = floorf(py), fx0 = floorf(px);
            float wy1 = py - fy0, wx1 = px - fx0;
            float wy0 = 1.f - wy1, wx0 = 1.f - wx1;
            int iy0 = (int)fy0, ix0 = (int)fx0;
            int iy1 = iy0 + 1, ix1 = ix0 + 1;
            bool vy0 = ((unsigned)iy0 < 64u), vy1 = ((unsigned)iy1 < 64u);
            bool vx0 = ((unsigned)ix0 < 64u), vx1 = ((unsigned)ix1 < 64u);
            float w00 = (vy0 && vx0) ? wy0 * wx0 : 0.f;
            float w01 = (vy0 && vx1) ? wy0 * wx1 : 0.f;
            float w10 = (vy1 && vx0) ? wy1 * wx0 : 0.f;
            float w11 = (vy1 && vx1) ? wy1 * wx1 : 0.f;
            int cy0 = min(max(iy0, 0), 63), cy1 = min(max(iy1, 0), 63);
            int cx0 = min(max(ix0, 0), 63), cx1 = min(max(ix1, 0), 63);
            int i00 = cy0 * 64 + cx0, i01 = cy0 * 64 + cx1;
            int i10 = cy1 * 64 + cx0, i11 = cy1 * 64 + cx1;

            const float* hp = hb;
            for (int cl = 0; cl < 32; cl++, hp += HW) {
                float s = w00 * hp[i00] + w01 * hp[i01]
                        + w10 * hp[i10] + w11 * hp[i11];
                const float* wr = ws + (cl * 9 + k2) * NOFF;
#pragma unroll
                for (int op = 0; op < 9; op++) {
                    float2 w = *(const float2*)&wr[2 * op];
                    acc[2 * op]     = fmaf(s, w.x, acc[2 * op]);
                    acc[2 * op + 1] = fmaf(s, w.y, acc[2 * op + 1]);
                }
            }
        }
    } else {
        for (int k2 = 0; k2 < 9; k2++) {
            int yy = y - 1 + k2 / 3, xx = x - 1 + k2 % 3;
            bool v = ((unsigned)yy < 64u) && ((unsigned)xx < 64u);
            int idx = v ? (yy * 64 + xx) : 0;
            const float* hp = hb;
            for (int cl = 0; cl < 32; cl++, hp += HW) {
                float s = v ? hp[idx] : 0.f;
                const float* wr = ws + (cl * 9 + k2) * NOFF;
#pragma unroll
                for (int op = 0; op < 9; op++) {
                    float2 w = *(const float2*)&wr[2 * op];
                    acc[2 * op]     = fmaf(s, w.x, acc[2 * op]);
                    acc[2 * op + 1] = fmaf(s, w.y, acc[2 * op + 1]);
                }
            }
        }
    }

    float* dst = partOut + chunk * PCH + b * NOFF * HW + y * 64 + x;
#pragma unroll
    for (int o = 0; o < NOFF; o++) dst[o * HW] = acc[o];
}

// ---------------------------------------------------------------------------
// K4: 128-oc deformable conv — tf32 mma GEMM v4: register-pipelined gathers.
// Tile 32px x 128oc, 128 thr, grid 1024. Per chunk: compute+STS from regs,
// issue next chunk's 32 raw corner LDGs into regs (retire behind MMA).
// ---------------------------------------------------------------------------
__device__ __forceinline__ void mma_tf32(float* d, const unsigned* a,
                                         unsigned b0, unsigned b1) {
    asm volatile(
        "mma.sync.aligned.m16n8k8.row.col.f32.tf32.tf32.f32 "
        "{%0,%1,%2,%3}, {%4,%5,%6,%7}, {%8,%9}, {%0,%1,%2,%3};"
        : "+f"(d[0]), "+f"(d[1]), "+f"(d[2]), "+f"(d[3])
        : "r"(a[0]), "r"(a[1]), "r"(a[2]), "r"(a[3]), "r"(b0), "r"(b1));
}

__global__ void __launch_bounds__(128) k_dconv128_mma(
        const float* __restrict__ obias,    // odc_b
        const float* __restrict__ bias,     // dc_b
        float* __restrict__ out) {
    __shared__ float4   s_wq[288];      // bilinear weights [k2*32+px]
    __shared__ int4     s_iq[288];      // corner indices
    __shared__ unsigned s_a[32][40];    // tf32 A tile [k][px], pad 40
    __shared__ unsigned s_b[32][136];   // tf32 B tile [k][oc], pad 136

    int tid = threadIdx.x;
    int blk = blockIdx.x;               // 1024 blocks
    int row = blk >> 1;
    int b = row >> 6, y = row & 63, x0 = (blk & 1) * 32;

    // Phase 0: offsets (4-partial sum + bias) -> bilinear tables, 32px x 9 taps
    for (int t = tid; t < 288; t += 128) {
        int px = t & 31, k2 = t >> 5;
        int x = x0 + px;
        int obase = b * NOFF * HW + y * 64 + x;
        float dy = obias[2 * k2], dx = obias[2 * k2 + 1];
        int oy = obase + (2 * k2) * HW, ox = oy + HW;
#pragma unroll
        for (int k = 0; k < 4; k++) {
            dy += g_part2[k * PCH + oy];
            dx += g_part2[k * PCH + ox];
        }
        float py  = (float)(y - 1 + k2 / 3) + dy;
        float pxf = (float)(x - 1 + k2 % 3) + dx;
        float fy0 = floorf(py), fx0 = floorf(pxf);
        float wy1 = py - fy0, wx1 = pxf - fx0;
        float wy0 = 1.f - wy1, wx0 = 1.f - wx1;
        int iy0 = (int)fy0, ix0 = (int)fx0;
        int iy1 = iy0 + 1, ix1 = ix0 + 1;
        bool vy0 = ((unsigned)iy0 < 64u), vy1 = ((unsigned)iy1 < 64u);
        bool vx0 = ((unsigned)ix0 < 64u), vx1 = ((unsigned)ix1 < 64u);
        float4 w;
        w.x = (vy0 && vx0) ? wy0 * wx0 : 0.f;
        w.y = (vy0 && vx1) ? wy0 * wx1 : 0.f;
        w.z = (vy1 && vx0) ? wy1 * wx0 : 0.f;
        w.w = (vy1 && vx1) ? wy1 * wx1 : 0.f;
        int cy0 = min(max(iy0, 0), 63), cy1 = min(max(iy1, 0), 63);
        int cx0 = min(max(ix0, 0), 63), cx1 = min(max(ix1, 0), 63);
        s_wq[t] = w;
        s_iq[t] = make_int4(cy0 * 64 + cx0, cy0 * 64 + cx1,
                            cy1 * 64 + cx0, cy1 * 64 + cx1);
    }
    __syncthreads();

    int lane = tid & 31, warp = tid >> 5;
    int ocw = warp * 32;                // warp oc base (all warps share 32 px)
    int gid = lane >> 2, tig = lane & 3;

    float acc[2][4][4];
#pragma unroll
    for (int mt = 0; mt < 2; mt++)
#pragma unroll
        for (int nt = 0; nt < 4; nt++)
#pragma unroll
            for (int q = 0; q < 4; q++) acc[mt][nt][q] = 0.f;

    int px_s = tid & 31, cl0 = (tid >> 5) * 8;   // 8 samples/thread
    const float* hb = g_h + (b << 7) * HW;

    // Gather pipeline registers: raw corner values + bilinear weights
    float r0[8], r1[8], r2[8], r3[8];
    float4 wA;

    // Prefetch chunk 0 (pure loads, 32-deep MLP)
    {
        int k2 = 0, c0 = 0;
        wA = s_wq[k2 * 32 + px_s];
        int4 ix = s_iq[k2 * 32 + px_s];
        const float* hp = hb + (c0 + cl0) * HW;
#pragma unroll
        for (int i = 0; i < 8; i++, hp += HW) {
            r0[i] = hp[ix.x]; r1[i] = hp[ix.y];
            r2[i] = hp[ix.z]; r3[i] = hp[ix.w];
        }
    }

    for (int kc = 0; kc < 36; kc++) {
        // Stage B tile via cp.async: 1024 uint4 / 128 thr = 8 each
        {
            const uint4* src = (const uint4*)g_wt2 + kc * 1024;
#pragma unroll
            for (int j = 0; j < 8; j++) {
                int i = tid + j * 128;
                unsigned dst = (unsigned)__cvta_generic_to_shared(
                    &s_b[i >> 5][(i & 31) * 4]);
                asm volatile("cp.async.cg.shared.global [%0], [%1], 16;"
                             :: "r"(dst), "l"(src + i));
            }
            asm volatile("cp.async.commit_group;");
        }
        // Compute+STS chunk kc from registers (consumes r*, wA)
        {
#pragma unroll
            for (int i = 0; i < 8; i++) {
                float v = wA.x * r0[i] + wA.y * r1[i]
                        + wA.z * r2[i] + wA.w * r3[i];
                unsigned t32;
                asm("cvt.rna.tf32.f32 %0, %1;" : "=r"(t32) : "f"(v));
                s_a[cl0 + i][px_s] = t32;
            }
        }
        // Prefetch chunk kc+1 (loads retire behind MMA below)
        if (kc < 35) {
            int kn = kc + 1;
            int k2 = kn >> 2, c0 = (kn & 3) * 32;
            wA = s_wq[k2 * 32 + px_s];
            int4 ix = s_iq[k2 * 32 + px_s];
            const float* hp = hb + (c0 + cl0) * HW;
#pragma unroll
            for (int i = 0; i < 8; i++, hp += HW) {
                r0[i] = hp[ix.x]; r1[i] = hp[ix.y];
                r2[i] = hp[ix.z]; r3[i] = hp[ix.w];
            }
        }
        asm volatile("cp.async.wait_group 0;");
        __syncthreads();

        // MMA phase: 4 k8-steps x (2 m-tiles x 4 n-tiles)
#pragma unroll
        for (int k0 = 0; k0 < 32; k0 += 8) {
            unsigned a[2][4];
#pragma unroll
            for (int mt = 0; mt < 2; mt++) {
                int pxb = mt * 16;
                a[mt][0] = s_a[k0 + tig][pxb + gid];
                a[mt][1] = s_a[k0 + tig][pxb + gid + 8];
                a[mt][2] = s_a[k0 + tig + 4][pxb + gid];
                a[mt][3] = s_a[k0 + tig + 4][pxb + gid + 8];
            }
#pragma unroll
            for (int nt = 0; nt < 4; nt++) {
                unsigned b0 = s_b[k0 + tig][ocw + nt * 8 + gid];
                unsigned b1 = s_b[k0 + tig + 4][ocw + nt * 8 + gid];
                mma_tf32(acc[0][nt], a[0], b0, b1);
                mma_tf32(acc[1][nt], a[1], b0, b1);
            }
        }
        __syncthreads();
    }

    // Epilogue: bias + stores
    int obase2 = (b << 7) * HW + y * 64 + x0;
#pragma unroll
    for (int nt = 0; nt < 4; nt++) {
        int oc0 = ocw + nt * 8 + 2 * tig;
        float bs0 = bias[oc0], bs1 = bias[oc0 + 1];
#pragma unroll
        for (int mt = 0; mt < 2; mt++) {
            int px0 = mt * 16 + gid;
            out[obase2 + oc0 * HW + px0]           = acc[mt][nt][0] + bs0;
            out[obase2 + (oc0 + 1) * HW + px0]     = acc[mt][nt][1] + bs1;
            out[obase2 + oc0 * HW + px0 + 8]       = acc[mt][nt][2] + bs0;
            out[obase2 + (oc0 + 1) * HW + px0 + 8] = acc[mt][nt][3] + bs1;
        }
    }
}

// ---------------------------------------------------------------------------
// Launch: 4 launches; index 3 (ncu's profiled slot) = mma128.
// Input order: x, bn_gamma, bn_beta, bn_mean, bn_var,
// off_w, off_b, odc_w, odc_b, dc_w, dc_b. Output: float32 [8,128,64,64].
// ---------------------------------------------------------------------------
extern "C" void kernel_launch(void* const* d_in, const int* in_sizes, int n_in,
                              void* d_out, int out_size) {
    const float* x     = (const float*)d_in[0];
    const float* gamma = (const float*)d_in[1];
    const float* beta  = (const float*)d_in[2];
    const float* mean  = (const float*)d_in[3];
    const float* var   = (const float*)d_in[4];
    const float* off_w = (const float*)d_in[5];
    const float* off_b = (const float*)d_in[6];
    const float* odc_w = (const float*)d_in[7];
    const float* odc_b = (const float*)d_in[8];
    const float* dc_w  = (const float*)d_in[9];
    const float* dc_b  = (const float*)d_in[10];
    float* out = (float*)d_out;

    float *wtA, *wtB, *part, *part2;
    cudaGetSymbolAddress((void**)&wtA,   g_wtA);
    cudaGetSymbolAddress((void**)&wtB,   g_wtB);
    cudaGetSymbolAddress((void**)&part,  g_part);
    cudaGetSymbolAddress((void**)&part2, g_part2);

    k_setup<<<4834, 256>>>(x, gamma, beta, mean, var, dc_w, off_w, odc_w); // 0
    k_dc18v2<<<dim3(256, 4), 128>>>(nullptr, nullptr, wtA, part);          // 1
    k_dc18v2<<<dim3(256, 4), 128>>>(part, off_b, wtB, part2);              // 2
    k_dconv128_mma<<<1024, 128>>>(odc_b, dc_b, out);                       // 3 <- prof
}